// round 13
// baseline (speedup 1.0000x reference)
#include <cuda_runtime.h>
#include <cuda_bf16.h>
#include <cstdint>

// ---------------------------------------------------------------------------
// Problem constants
// ---------------------------------------------------------------------------
#define DIM   4096
#define LAT   32768
#define NB    4096
#define TOPK  64

// GEMM tiling (single bf16 term)
#define BM      128
#define BN      128
#define BK      64                // bf16 k-elems per stage (128B per tile row)
#define NKSTEP  (DIM / BK)        // 64
#define STAGES  3
#define A_STG   16384             // 128 rows * 128 B
#define B_STG   16384
#define STG     (A_STG + B_STG)   // 32 KB per stage

// candidate band: single-bf16 GEMM abs error sigma ~7.5e-4; delta = 40 sigma
#define BAND_DELTA 0.03f
#define MAXC 512

// ---------------------------------------------------------------------------
// Device scratch (__device__ globals; no allocation)
// ---------------------------------------------------------------------------
__device__ __nv_bfloat16 g_Ahi[(size_t)NB * DIM];     //  32 MB
__device__ __nv_bfloat16 g_Bhi[(size_t)LAT * DIM];    // 256 MB
__device__ float g_zpre[(size_t)NB * LAT];            // 512 MB
__device__ float g_WdT[(size_t)LAT * DIM];            // 512 MB
__device__ int   g_selidx[NB * TOPK];
__device__ float g_selval[NB * TOPK];

// ---------------------------------------------------------------------------
// PTX helpers (sm_80-level features only; plain compute_103-safe)
// ---------------------------------------------------------------------------
__device__ __forceinline__ uint32_t smem_u32(const void* p) {
    uint32_t a;
    asm("{ .reg .u64 t; cvta.to.shared.u64 t, %1; cvt.u32.u64 %0, t; }" : "=r"(a) : "l"(p));
    return a;
}

#define CP_ASYNC16(dst, src) \
    asm volatile("cp.async.cg.shared.global [%0], [%1], 16;" :: "r"(dst), "l"(src))
#define CP_COMMIT()  asm volatile("cp.async.commit_group;")
#define CP_WAIT(n)   asm volatile("cp.async.wait_group %0;" :: "n"(n))

#define LDSM4(R, addr) \
    asm volatile("ldmatrix.sync.aligned.m8n8.x4.shared.b16 {%0,%1,%2,%3}, [%4];" \
                 : "=r"((R)[0]), "=r"((R)[1]), "=r"((R)[2]), "=r"((R)[3]) : "r"(addr))

#define MMA_BF16(C, A, B0, B1) \
    asm volatile("mma.sync.aligned.m16n8k16.row.col.f32.bf16.bf16.f32 " \
                 "{%0,%1,%2,%3}, {%4,%5,%6,%7}, {%8,%9}, {%0,%1,%2,%3};" \
                 : "+f"((C)[0]), "+f"((C)[1]), "+f"((C)[2]), "+f"((C)[3]) \
                 : "r"((A)[0]), "r"((A)[1]), "r"((A)[2]), "r"((A)[3]), "r"(B0), "r"(B1))

// ---------------------------------------------------------------------------
// bf16 conversion kernels (rank-only precision; exact values recomputed later)
// ---------------------------------------------------------------------------
__global__ void __launch_bounds__(256) convert_h_kernel(const float* __restrict__ h) {
    size_t t = (size_t)blockIdx.x * 256 + threadIdx.x;
    float2 f = ((const float2*)h)[t];
    __nv_bfloat162 v;
    v.x = __float2bfloat16(f.x);
    v.y = __float2bfloat16(f.y);
    ((__nv_bfloat162*)g_Ahi)[t] = v;
}

__global__ void __launch_bounds__(256) convert_w_kernel(const float* __restrict__ W) {
    size_t t = (size_t)blockIdx.x * 256 + threadIdx.x;
    float2 f = ((const float2*)W)[t];
    __nv_bfloat162 v;
    v.x = __float2bfloat16(f.x);
    v.y = __float2bfloat16(f.y);
    ((__nv_bfloat162*)g_Bhi)[t] = v;
}

// ---------------------------------------------------------------------------
// Transpose W_dec [DIM, LAT] -> g_WdT [LAT, DIM]
// ---------------------------------------------------------------------------
__global__ void __launch_bounds__(256) transpose_kernel(const float* __restrict__ Wd) {
    __shared__ float tile[32][33];
    int lbase = blockIdx.x * 32, dbase = blockIdx.y * 32;
    int tx = threadIdx.x, ty = threadIdx.y;   // (32, 8)
#pragma unroll
    for (int j = 0; j < 4; ++j)
        tile[ty + j * 8][tx] = Wd[(size_t)(dbase + ty + j * 8) * LAT + lbase + tx];
    __syncthreads();
#pragma unroll
    for (int j = 0; j < 4; ++j)
        g_WdT[(size_t)(lbase + ty + j * 8) * DIM + dbase + tx] = tile[tx][ty + j * 8];
}

// ---------------------------------------------------------------------------
// Encode GEMM: z_pre ~= h @ W_enc^T, single bf16, mma.sync
// CTA 128x128, 8 warps (4M x 2N), 3-stage cp.async, SW128 swizzle, BK=64,
// 2 CTAs/SM. CP_COMMIT every iteration so CP_WAIT is ALWAYS binding (the
// missing-commit tail race was the R10/R12 correctness bug).
// ---------------------------------------------------------------------------
__device__ __forceinline__ void load_stage(uint32_t sbase, int slot, int kt,
                                           int m0, int n0, int tid) {
    uint32_t stg = sbase + slot * STG;
    int t = tid & 127;
    bool isB = tid >= 128;
    int base_row = isB ? n0 : m0;
    const __nv_bfloat16* src_base = isB ? g_Bhi : g_Ahi;
    uint32_t dst0 = stg + (isB ? A_STG : 0);
#pragma unroll
    for (int j = 0; j < 8; ++j) {
        int gid = j * 128 + t;
        int row = gid >> 3;        // 0..127
        int g   = gid & 7;         // 16B granule: k offset g*8 elems
        const __nv_bfloat16* src =
            src_base + (size_t)(base_row + row) * DIM + kt + g * 8;
        uint32_t col = (uint32_t)g * 16;
        uint32_t dst = dst0 + row * 128 + (col ^ (((uint32_t)row & 7) << 4));
        CP_ASYNC16(dst, src);
    }
}

__global__ void __launch_bounds__(256, 2) gemm_kernel() {
    extern __shared__ char smraw[];
    uint32_t sbase = (smem_u32(smraw) + 1023u) & ~1023u;

    int tid  = threadIdx.x;
    int lane = tid & 31;
    int wid  = tid >> 5;
    int m_tile = blockIdx.x & 31;       // M fastest -> B tiles shared by 32 CTAs
    int n_tile = blockIdx.x >> 5;
    int m0 = m_tile * BM, n0 = n_tile * BN;
    int mw = (wid & 3) * 32;
    int nw = (wid >> 2) * 64;

    float acc[2][8][4];
#pragma unroll
    for (int a = 0; a < 2; ++a)
#pragma unroll
        for (int b = 0; b < 8; ++b)
#pragma unroll
            for (int c = 0; c < 4; ++c) acc[a][b][c] = 0.0f;

    load_stage(sbase, 0, 0, m0, n0, tid);  CP_COMMIT();
    load_stage(sbase, 1, BK, m0, n0, tid); CP_COMMIT();

    int rowA0 = mw + (lane & 15);
    int rowB0 = nw + (lane & 7) + ((lane & 16) ? 8 : 0);
    uint32_t khA = (lane & 16) ? 16u : 0u;
    uint32_t khB = (lane & 8)  ? 16u : 0u;

    int cons = 0, prod = 2;
#pragma unroll 1
    for (int ks = 0; ks < NKSTEP; ++ks) {
        CP_WAIT(STAGES - 2);
        __syncthreads();

        int nxt = ks + STAGES - 1;
        if (nxt < NKSTEP) load_stage(sbase, prod, nxt * BK, m0, n0, tid);
        CP_COMMIT();    // unconditional: keeps group accounting uniform

        uint32_t sA = sbase + cons * STG;
        uint32_t sB = sA + A_STG;

#pragma unroll
        for (int ksub = 0; ksub < 4; ++ksub) {      // 4 x k16 per 128B row
            uint32_t aH[2][4], bH[8][2];
            uint32_t kb = (uint32_t)ksub * 32;

#pragma unroll
            for (int mi = 0; mi < 2; ++mi) {
                int row = rowA0 + mi * 16;
                uint32_t xr = ((uint32_t)row & 7) << 4;
                LDSM4(aH[mi], sA + row * 128 + ((kb + khA) ^ xr));
            }
#pragma unroll
            for (int ni = 0; ni < 4; ++ni) {
                int row = rowB0 + ni * 16;
                uint32_t xr = ((uint32_t)row & 7) << 4;
                uint32_t rh[4];
                LDSM4(rh, sB + row * 128 + ((kb + khB) ^ xr));
                bH[2 * ni][0] = rh[0]; bH[2 * ni][1] = rh[1];
                bH[2 * ni + 1][0] = rh[2]; bH[2 * ni + 1][1] = rh[3];
            }
#pragma unroll
            for (int mi = 0; mi < 2; ++mi)
#pragma unroll
                for (int t8 = 0; t8 < 8; ++t8)
                    MMA_BF16(acc[mi][t8], aH[mi], bH[t8][0], bH[t8][1]);
        }

        cons = (cons == STAGES - 1) ? 0 : cons + 1;
        prod = (prod == STAGES - 1) ? 0 : prod + 1;
    }

#pragma unroll
    for (int mi = 0; mi < 2; ++mi) {
#pragma unroll
        for (int t8 = 0; t8 < 8; ++t8) {
            int row = m0 + mw + mi * 16 + (lane >> 2);
            int col = n0 + nw + t8 * 8 + (lane & 3) * 2;
            float2 v0 = make_float2(acc[mi][t8][0], acc[mi][t8][1]);
            float2 v1 = make_float2(acc[mi][t8][2], acc[mi][t8][3]);
            *(float2*)&g_zpre[(size_t)row * LAT + col]       = v0;
            *(float2*)&g_zpre[(size_t)(row + 8) * LAT + col] = v1;
        }
    }
}

// ---------------------------------------------------------------------------
// Per-row top-64: radix select on approximate keys, then EXACT fp64 dots for
// all candidates, exact ranking, exact fp32 output values.
// ---------------------------------------------------------------------------
__device__ __forceinline__ unsigned sortkey(float f) {
    unsigned b = __float_as_uint(f);
    return (b & 0x80000000u) ? ~b : (b | 0x80000000u);
}
__device__ __forceinline__ float unsortkey(unsigned u) {
    unsigned b = (u & 0x80000000u) ? (u & 0x7FFFFFFFu) : ~u;
    return __uint_as_float(b);
}

__global__ void __launch_bounds__(512, 1) topk_kernel(const float* __restrict__ h,
                                                      const float* __restrict__ W_enc,
                                                      const float* __restrict__ b_enc,
                                                      float* __restrict__ z_out) {
    extern __shared__ unsigned skeys[];        // 32768 keys = 128 KB
    __shared__ unsigned hist[256];
    __shared__ unsigned sh_prefix, sh_rem, sh_ncand;
    __shared__ int   cidx[MAXC];
    __shared__ float cval[MAXC];
    __shared__ unsigned char csel[MAXC];

    int row  = blockIdx.x;
    int tid  = threadIdx.x;
    int lane = tid & 31;
    int wid  = tid >> 5;
    const float* zp = g_zpre + (size_t)row * LAT;

    for (int i = tid; i < LAT; i += 512)
        skeys[i] = sortkey(zp[i] + b_enc[i]);
    if (tid == 0) { sh_prefix = 0; sh_rem = TOPK; sh_ncand = 0; }
    __syncthreads();

    // ---- radix select: approximate 64th-largest key ----
    for (int level = 3; level >= 0; --level) {
        if (tid < 256) hist[tid] = 0;
        __syncthreads();
        unsigned prefix = sh_prefix;
        unsigned pmask  = (level == 3) ? 0u : (0xFFFFFFFFu << ((level + 1) * 8));
        int shift = level * 8;
        for (int i = tid; i < LAT; i += 512) {
            unsigned k = skeys[i];
            if ((k & pmask) == prefix) atomicAdd(&hist[(k >> shift) & 255], 1u);
        }
        __syncthreads();
        if (tid == 0) {
            unsigned rem = sh_rem;
            int b = 255;
            for (; b > 0; --b) {
                unsigned c = hist[b];
                if (c >= rem) break;
                rem -= c;
            }
            sh_prefix = prefix | ((unsigned)b << shift);
            sh_rem = rem;
        }
        __syncthreads();
    }

    float    Tv    = unsortkey(sh_prefix);
    unsigned keyLo = sortkey(Tv - BAND_DELTA);

    // ---- candidates: everything that could be a true top-64 member ----
    for (int i = tid; i < LAT; i += 512) {
        if (skeys[i] >= keyLo) {
            unsigned s = atomicAdd(&sh_ncand, 1u);
            if (s < MAXC) cidx[s] = i;
        }
    }
    __syncthreads();
    int nc = (int)sh_ncand; if (nc > MAXC) nc = MAXC;

    // ---- exact fp64 dot per candidate (one warp per candidate) ----
    const float* hrow = h + (size_t)row * DIM;
    for (int c = wid; c < nc; c += 16) {
        int l = cidx[c];
        const float* wrow = W_enc + (size_t)l * DIM;
        double p = 0.0;
#pragma unroll 4
        for (int i = lane * 4; i < DIM; i += 128) {
            float4 hv = *(const float4*)(hrow + i);
            float4 wv = *(const float4*)(wrow + i);
            p = fma((double)hv.x, (double)wv.x, p);
            p = fma((double)hv.y, (double)wv.y, p);
            p = fma((double)hv.z, (double)wv.z, p);
            p = fma((double)hv.w, (double)wv.w, p);
        }
#pragma unroll
        for (int off = 16; off > 0; off >>= 1) p += __shfl_xor_sync(0xFFFFFFFFu, p, off);
        if (lane == 0) cval[c] = (float)(p + (double)b_enc[l]);
    }
    __syncthreads();

    // ---- exact ranking among candidates (jax tie order: lower idx first) ----
    if (tid < nc) {
        float v = cval[tid]; int id = cidx[tid];
        int r = 0;
        for (int m = 0; m < nc; ++m)
            if (cval[m] > v || (cval[m] == v && cidx[m] < id)) r++;
        csel[tid] = (r < TOPK) ? 1 : 0;
    }
    __syncthreads();

    // ---- dense z: zeros then scatter exact relu'd winners ----
    float* zr = z_out + (size_t)row * LAT;
    for (int i = tid; i < LAT; i += 512) zr[i] = 0.0f;
    __syncthreads();
    if (tid < nc && csel[tid]) {
        float relv = fmaxf(cval[tid], 0.0f);
        zr[cidx[tid]] = relv;
        int slot = 0;
        for (int m = 0; m < nc; ++m)
            if (csel[m] && cidx[m] < cidx[tid]) slot++;
        g_selidx[row * TOPK + slot] = cidx[tid];
        g_selval[row * TOPK + slot] = relv;
    }
}

// ---------------------------------------------------------------------------
// Sparse decode: h_hat[b] = b_dec + sum_k val_k * WdT[idx_k, :]
// ---------------------------------------------------------------------------
__global__ void __launch_bounds__(512) decode_kernel(const float* __restrict__ b_dec,
                                                     float* __restrict__ h_hat) {
    __shared__ int   sidx[TOPK];
    __shared__ float sval[TOPK];
    int b = blockIdx.x;
    if (threadIdx.x < TOPK) {
        sidx[threadIdx.x] = g_selidx[b * TOPK + threadIdx.x];
        sval[threadIdx.x] = g_selval[b * TOPK + threadIdx.x];
    }
    __syncthreads();

    int d0 = threadIdx.x * 8;
    float4 a0 = *(const float4*)(b_dec + d0);
    float4 a1 = *(const float4*)(b_dec + d0 + 4);
#pragma unroll 4
    for (int k = 0; k < TOPK; ++k) {
        const float4* w = (const float4*)(g_WdT + (size_t)sidx[k] * DIM + d0);
        float v = sval[k];
        float4 w0 = w[0], w1 = w[1];
        a0.x += v * w0.x; a0.y += v * w0.y; a0.z += v * w0.z; a0.w += v * w0.w;
        a1.x += v * w1.x; a1.y += v * w1.y; a1.z += v * w1.z; a1.w += v * w1.w;
    }
    *(float4*)(h_hat + (size_t)b * DIM + d0)     = a0;
    *(float4*)(h_hat + (size_t)b * DIM + d0 + 4) = a1;
}

// ---------------------------------------------------------------------------
// Launch: inputs h, W_enc, b_enc, W_dec, b_dec; out = [h_hat | z]
// ---------------------------------------------------------------------------
extern "C" void kernel_launch(void* const* d_in, const int* in_sizes, int n_in,
                              void* d_out, int out_size) {
    const float* h     = (const float*)d_in[0];
    const float* W_enc = (const float*)d_in[1];
    const float* b_enc = (const float*)d_in[2];
    const float* W_dec = (const float*)d_in[3];
    const float* b_dec = (const float*)d_in[4];
    float* out   = (float*)d_out;
    float* h_hat = out;
    float* z_out = out + (size_t)NB * DIM;

    const int GEMM_SMEM = STAGES * STG + 1024;    // 97 KB -> 2 CTAs/SM
    cudaFuncSetAttribute(gemm_kernel, cudaFuncAttributeMaxDynamicSharedMemorySize, GEMM_SMEM);
    cudaFuncSetAttribute(topk_kernel, cudaFuncAttributeMaxDynamicSharedMemorySize, LAT * 4);

    // 1) bf16 conversions (rank-only precision)
    convert_h_kernel<<<(unsigned)((size_t)NB * DIM / 2 / 256), 256>>>(h);
    convert_w_kernel<<<(unsigned)((size_t)LAT * DIM / 2 / 256), 256>>>(W_enc);

    // 2) transpose W_dec for coalesced sparse decode
    transpose_kernel<<<dim3(LAT / 32, DIM / 32), dim3(32, 8)>>>(W_dec);

    // 3) encode GEMM (single bf16, mma.sync, always-commit pipeline)
    gemm_kernel<<<(NB / BM) * (LAT / BN), 256, GEMM_SMEM>>>();

    // 4) top-64: radix select + exact fp64 candidate refinement
    topk_kernel<<<NB, 512, LAT * 4>>>(h, W_enc, b_enc, z_out);

    // 5) sparse decode
    decode_kernel<<<NB, 512>>>(b_dec, h_hat);

    (void)in_sizes; (void)n_in; (void)out_size;
}

// round 15
// speedup vs baseline: 2.2119x; 2.2119x over previous
#include <cuda_runtime.h>
#include <cuda_bf16.h>
#include <cstdint>

// ---------------------------------------------------------------------------
// Problem constants
// ---------------------------------------------------------------------------
#define DIM   4096
#define LAT   32768
#define NB    4096
#define TOPK  64

// GEMM tiling (single bf16 term)
#define BM      128
#define BN      128
#define BK      64                // bf16 k-elems per stage (128B per tile row)
#define NKSTEP  (DIM / BK)        // 64
#define STAGES  3
#define A_STG   16384             // 128 rows * 128 B
#define B_STG   16384
#define STG     (A_STG + B_STG)   // 32 KB per stage

// candidate band: single-bf16 GEMM abs error sigma ~1.1e-3; delta = 27 sigma
#define BAND_DELTA 0.03f
#define MAXC 512

// ---------------------------------------------------------------------------
// Device scratch (__device__ globals; no allocation)
// ---------------------------------------------------------------------------
__device__ __nv_bfloat16 g_Ahi[(size_t)NB * DIM];     //  32 MB
__device__ __nv_bfloat16 g_Bhi[(size_t)LAT * DIM];    // 256 MB
__device__ float g_zpre[(size_t)NB * LAT];            // 512 MB
__device__ float g_WdT[(size_t)LAT * DIM];            // 512 MB
__device__ int   g_selidx[NB * TOPK];
__device__ float g_selval[NB * TOPK];

// ---------------------------------------------------------------------------
// PTX helpers (sm_80-level features only; plain compute_103-safe)
// ---------------------------------------------------------------------------
__device__ __forceinline__ uint32_t smem_u32(const void* p) {
    uint32_t a;
    asm("{ .reg .u64 t; cvta.to.shared.u64 t, %1; cvt.u32.u64 %0, t; }" : "=r"(a) : "l"(p));
    return a;
}

#define CP_ASYNC16(dst, src) \
    asm volatile("cp.async.cg.shared.global [%0], [%1], 16;" :: "r"(dst), "l"(src))
#define CP_COMMIT()  asm volatile("cp.async.commit_group;")
#define CP_WAIT(n)   asm volatile("cp.async.wait_group %0;" :: "n"(n))

#define LDSM4(R, addr) \
    asm volatile("ldmatrix.sync.aligned.m8n8.x4.shared.b16 {%0,%1,%2,%3}, [%4];" \
                 : "=r"((R)[0]), "=r"((R)[1]), "=r"((R)[2]), "=r"((R)[3]) : "r"(addr))

#define MMA_BF16(C, A, B0, B1) \
    asm volatile("mma.sync.aligned.m16n8k16.row.col.f32.bf16.bf16.f32 " \
                 "{%0,%1,%2,%3}, {%4,%5,%6,%7}, {%8,%9}, {%0,%1,%2,%3};" \
                 : "+f"((C)[0]), "+f"((C)[1]), "+f"((C)[2]), "+f"((C)[3]) \
                 : "r"((A)[0]), "r"((A)[1]), "r"((A)[2]), "r"((A)[3]), "r"(B0), "r"(B1))

// ---------------------------------------------------------------------------
// bf16 conversion kernels (rank-only precision; exact values recomputed later)
// ---------------------------------------------------------------------------
__global__ void __launch_bounds__(256) convert_h_kernel(const float* __restrict__ h) {
    size_t t = (size_t)blockIdx.x * 256 + threadIdx.x;
    float2 f = ((const float2*)h)[t];
    __nv_bfloat162 v;
    v.x = __float2bfloat16(f.x);
    v.y = __float2bfloat16(f.y);
    ((__nv_bfloat162*)g_Ahi)[t] = v;
}

__global__ void __launch_bounds__(256) convert_w_kernel(const float* __restrict__ W) {
    size_t t = (size_t)blockIdx.x * 256 + threadIdx.x;
    float2 f = ((const float2*)W)[t];
    __nv_bfloat162 v;
    v.x = __float2bfloat16(f.x);
    v.y = __float2bfloat16(f.y);
    ((__nv_bfloat162*)g_Bhi)[t] = v;
}

// ---------------------------------------------------------------------------
// Transpose W_dec [DIM, LAT] -> g_WdT [LAT, DIM]
// ---------------------------------------------------------------------------
__global__ void __launch_bounds__(256) transpose_kernel(const float* __restrict__ Wd) {
    __shared__ float tile[32][33];
    int lbase = blockIdx.x * 32, dbase = blockIdx.y * 32;
    int tx = threadIdx.x, ty = threadIdx.y;   // (32, 8)
#pragma unroll
    for (int j = 0; j < 4; ++j)
        tile[ty + j * 8][tx] = Wd[(size_t)(dbase + ty + j * 8) * LAT + lbase + tx];
    __syncthreads();
#pragma unroll
    for (int j = 0; j < 4; ++j)
        g_WdT[(size_t)(lbase + ty + j * 8) * DIM + dbase + tx] = tile[tx][ty + j * 8];
}

// ---------------------------------------------------------------------------
// Encode GEMM: z_pre ~= h @ W_enc^T, single bf16, mma.sync
// CTA 128x128, 8 warps (4M x 2N), 3-stage cp.async, SW128 swizzle, BK=64,
// 2 CTAs/SM. CP_COMMIT every iteration so CP_WAIT is ALWAYS binding.
// ---------------------------------------------------------------------------
__device__ __forceinline__ void load_stage(uint32_t sbase, int slot, int kt,
                                           int m0, int n0, int tid) {
    uint32_t stg = sbase + slot * STG;
    int t = tid & 127;
    bool isB = tid >= 128;
    int base_row = isB ? n0 : m0;
    const __nv_bfloat16* src_base = isB ? g_Bhi : g_Ahi;
    uint32_t dst0 = stg + (isB ? A_STG : 0);
#pragma unroll
    for (int j = 0; j < 8; ++j) {
        int gid = j * 128 + t;
        int row = gid >> 3;        // 0..127
        int g   = gid & 7;         // 16B granule: k offset g*8 elems
        const __nv_bfloat16* src =
            src_base + (size_t)(base_row + row) * DIM + kt + g * 8;
        uint32_t col = (uint32_t)g * 16;
        uint32_t dst = dst0 + row * 128 + (col ^ (((uint32_t)row & 7) << 4));
        CP_ASYNC16(dst, src);
    }
}

__global__ void __launch_bounds__(256, 2) gemm_kernel() {
    extern __shared__ char smraw[];
    uint32_t sbase = (smem_u32(smraw) + 1023u) & ~1023u;

    int tid  = threadIdx.x;
    int lane = tid & 31;
    int wid  = tid >> 5;
    int m_tile = blockIdx.x & 31;       // M fastest -> B tiles shared by 32 CTAs
    int n_tile = blockIdx.x >> 5;
    int m0 = m_tile * BM, n0 = n_tile * BN;
    int mw = (wid & 3) * 32;
    int nw = (wid >> 2) * 64;

    float acc[2][8][4];
#pragma unroll
    for (int a = 0; a < 2; ++a)
#pragma unroll
        for (int b = 0; b < 8; ++b)
#pragma unroll
            for (int c = 0; c < 4; ++c) acc[a][b][c] = 0.0f;

    load_stage(sbase, 0, 0, m0, n0, tid);  CP_COMMIT();
    load_stage(sbase, 1, BK, m0, n0, tid); CP_COMMIT();

    int rowA0 = mw + (lane & 15);
    int rowB0 = nw + (lane & 7) + ((lane & 16) ? 8 : 0);
    uint32_t khA = (lane & 16) ? 16u : 0u;
    uint32_t khB = (lane & 8)  ? 16u : 0u;

    int cons = 0, prod = 2;
#pragma unroll 1
    for (int ks = 0; ks < NKSTEP; ++ks) {
        CP_WAIT(STAGES - 2);
        __syncthreads();

        int nxt = ks + STAGES - 1;
        if (nxt < NKSTEP) load_stage(sbase, prod, nxt * BK, m0, n0, tid);
        CP_COMMIT();    // unconditional: keeps group accounting uniform

        uint32_t sA = sbase + cons * STG;
        uint32_t sB = sA + A_STG;

#pragma unroll
        for (int ksub = 0; ksub < 4; ++ksub) {      // 4 x k16 per 128B row
            uint32_t aH[2][4], bH[8][2];
            uint32_t kb = (uint32_t)ksub * 32;

#pragma unroll
            for (int mi = 0; mi < 2; ++mi) {
                int row = rowA0 + mi * 16;
                uint32_t xr = ((uint32_t)row & 7) << 4;
                LDSM4(aH[mi], sA + row * 128 + ((kb + khA) ^ xr));
            }
#pragma unroll
            for (int ni = 0; ni < 4; ++ni) {
                int row = rowB0 + ni * 16;
                uint32_t xr = ((uint32_t)row & 7) << 4;
                uint32_t rh[4];
                LDSM4(rh, sB + row * 128 + ((kb + khB) ^ xr));
                bH[2 * ni][0] = rh[0]; bH[2 * ni][1] = rh[1];
                bH[2 * ni + 1][0] = rh[2]; bH[2 * ni + 1][1] = rh[3];
            }
#pragma unroll
            for (int mi = 0; mi < 2; ++mi)
#pragma unroll
                for (int t8 = 0; t8 < 8; ++t8)
                    MMA_BF16(acc[mi][t8], aH[mi], bH[t8][0], bH[t8][1]);
        }

        cons = (cons == STAGES - 1) ? 0 : cons + 1;
        prod = (prod == STAGES - 1) ? 0 : prod + 1;
    }

#pragma unroll
    for (int mi = 0; mi < 2; ++mi) {
#pragma unroll
        for (int t8 = 0; t8 < 8; ++t8) {
            int row = m0 + mw + mi * 16 + (lane >> 2);
            int col = n0 + nw + t8 * 8 + (lane & 3) * 2;
            float2 v0 = make_float2(acc[mi][t8][0], acc[mi][t8][1]);
            float2 v1 = make_float2(acc[mi][t8][2], acc[mi][t8][3]);
            *(float2*)&g_zpre[(size_t)row * LAT + col]       = v0;
            *(float2*)&g_zpre[(size_t)(row + 8) * LAT + col] = v1;
        }
    }
}

// ---------------------------------------------------------------------------
// Per-row top-64: radix select on approximate keys, then COMPENSATED fp32
// (dot2: TwoProd + TwoSum, error ~eps^2 == true value) dots for all
// candidates, exact ranking, exact output values. NO bulk fp64 (R13: +7.5ms),
// NO plain fp32 (R12/R14: boundary-swap rank error vs reference).
// ---------------------------------------------------------------------------
__device__ __forceinline__ unsigned sortkey(float f) {
    unsigned b = __float_as_uint(f);
    return (b & 0x80000000u) ? ~b : (b | 0x80000000u);
}
__device__ __forceinline__ float unsortkey(unsigned u) {
    unsigned b = (u & 0x80000000u) ? (u & 0x7FFFFFFFu) : ~u;
    return __uint_as_float(b);
}

// accumulate a*b into (s, c) with full compensation
__device__ __forceinline__ void dot2_acc(float a, float b, float& s, float& c) {
    float ph = a * b;
    float pl = fmaf(a, b, -ph);      // exact product residual
    float t  = s + ph;               // TwoSum
    float z  = t - s;
    float e  = (s - (t - z)) + (ph - z);
    s = t;
    c += e + pl;
}

__global__ void __launch_bounds__(512, 1) topk_kernel(const float* __restrict__ h,
                                                      const float* __restrict__ W_enc,
                                                      const float* __restrict__ b_enc,
                                                      float* __restrict__ z_out) {
    extern __shared__ unsigned skeys[];        // 32768 keys = 128 KB
    __shared__ unsigned hist[256];
    __shared__ unsigned sh_prefix, sh_rem, sh_ncand;
    __shared__ int   cidx[MAXC];
    __shared__ float cval[MAXC];
    __shared__ unsigned char csel[MAXC];

    int row  = blockIdx.x;
    int tid  = threadIdx.x;
    int lane = tid & 31;
    int wid  = tid >> 5;
    const float* zp = g_zpre + (size_t)row * LAT;

    for (int i = tid; i < LAT; i += 512)
        skeys[i] = sortkey(zp[i] + b_enc[i]);
    if (tid == 0) { sh_prefix = 0; sh_rem = TOPK; sh_ncand = 0; }
    __syncthreads();

    // ---- radix select: approximate 64th-largest key ----
    for (int level = 3; level >= 0; --level) {
        if (tid < 256) hist[tid] = 0;
        __syncthreads();
        unsigned prefix = sh_prefix;
        unsigned pmask  = (level == 3) ? 0u : (0xFFFFFFFFu << ((level + 1) * 8));
        int shift = level * 8;
        for (int i = tid; i < LAT; i += 512) {
            unsigned k = skeys[i];
            if ((k & pmask) == prefix) atomicAdd(&hist[(k >> shift) & 255], 1u);
        }
        __syncthreads();
        if (tid == 0) {
            unsigned rem = sh_rem;
            int b = 255;
            for (; b > 0; --b) {
                unsigned c = hist[b];
                if (c >= rem) break;
                rem -= c;
            }
            sh_prefix = prefix | ((unsigned)b << shift);
            sh_rem = rem;
        }
        __syncthreads();
    }

    float    Tv    = unsortkey(sh_prefix);
    unsigned keyLo = sortkey(Tv - BAND_DELTA);

    // ---- candidates: everything that could be a true top-64 member ----
    for (int i = tid; i < LAT; i += 512) {
        if (skeys[i] >= keyLo) {
            unsigned s = atomicAdd(&sh_ncand, 1u);
            if (s < MAXC) cidx[s] = i;
        }
    }
    __syncthreads();
    int nc = (int)sh_ncand; if (nc > MAXC) nc = MAXC;

    // ---- compensated fp32 dot per candidate (one warp per candidate) ----
    const float* hrow = h + (size_t)row * DIM;
    for (int c = wid; c < nc; c += 16) {
        int l = cidx[c];
        const float* wrow = W_enc + (size_t)l * DIM;
        float s = 0.0f, comp = 0.0f;
#pragma unroll 4
        for (int i = lane * 4; i < DIM; i += 128) {
            float4 hv = *(const float4*)(hrow + i);
            float4 wv = *(const float4*)(wrow + i);
            dot2_acc(hv.x, wv.x, s, comp);
            dot2_acc(hv.y, wv.y, s, comp);
            dot2_acc(hv.z, wv.z, s, comp);
            dot2_acc(hv.w, wv.w, s, comp);
        }
        // cross-lane reduce in fp64 (tiny op count; bulk work stayed fp32)
        double p = (double)s + (double)comp;
#pragma unroll
        for (int off = 16; off > 0; off >>= 1) p += __shfl_xor_sync(0xFFFFFFFFu, p, off);
        if (lane == 0) cval[c] = (float)(p + (double)b_enc[l]);
    }
    __syncthreads();

    // ---- exact ranking among candidates (jax tie order: lower idx first) ----
    if (tid < nc) {
        float v = cval[tid]; int id = cidx[tid];
        int r = 0;
        for (int m = 0; m < nc; ++m)
            if (cval[m] > v || (cval[m] == v && cidx[m] < id)) r++;
        csel[tid] = (r < TOPK) ? 1 : 0;
    }
    __syncthreads();

    // ---- dense z: zeros then scatter exact relu'd winners ----
    float* zr = z_out + (size_t)row * LAT;
    for (int i = tid; i < LAT; i += 512) zr[i] = 0.0f;
    __syncthreads();
    if (tid < nc && csel[tid]) {
        float relv = fmaxf(cval[tid], 0.0f);
        zr[cidx[tid]] = relv;
        int slot = 0;
        for (int m = 0; m < nc; ++m)
            if (csel[m] && cidx[m] < cidx[tid]) slot++;
        g_selidx[row * TOPK + slot] = cidx[tid];
        g_selval[row * TOPK + slot] = relv;
    }
}

// ---------------------------------------------------------------------------
// Sparse decode: h_hat[b] = b_dec + sum_k val_k * WdT[idx_k, :]
// ---------------------------------------------------------------------------
__global__ void __launch_bounds__(512) decode_kernel(const float* __restrict__ b_dec,
                                                     float* __restrict__ h_hat) {
    __shared__ int   sidx[TOPK];
    __shared__ float sval[TOPK];
    int b = blockIdx.x;
    if (threadIdx.x < TOPK) {
        sidx[threadIdx.x] = g_selidx[b * TOPK + threadIdx.x];
        sval[threadIdx.x] = g_selval[b * TOPK + threadIdx.x];
    }
    __syncthreads();

    int d0 = threadIdx.x * 8;
    float4 a0 = *(const float4*)(b_dec + d0);
    float4 a1 = *(const float4*)(b_dec + d0 + 4);
#pragma unroll 4
    for (int k = 0; k < TOPK; ++k) {
        const float4* w = (const float4*)(g_WdT + (size_t)sidx[k] * DIM + d0);
        float v = sval[k];
        float4 w0 = w[0], w1 = w[1];
        a0.x += v * w0.x; a0.y += v * w0.y; a0.z += v * w0.z; a0.w += v * w0.w;
        a1.x += v * w1.x; a1.y += v * w1.y; a1.z += v * w1.z; a1.w += v * w1.w;
    }
    *(float4*)(h_hat + (size_t)b * DIM + d0)     = a0;
    *(float4*)(h_hat + (size_t)b * DIM + d0 + 4) = a1;
}

// ---------------------------------------------------------------------------
// Launch: inputs h, W_enc, b_enc, W_dec, b_dec; out = [h_hat | z]
// ---------------------------------------------------------------------------
extern "C" void kernel_launch(void* const* d_in, const int* in_sizes, int n_in,
                              void* d_out, int out_size) {
    const float* h     = (const float*)d_in[0];
    const float* W_enc = (const float*)d_in[1];
    const float* b_enc = (const float*)d_in[2];
    const float* W_dec = (const float*)d_in[3];
    const float* b_dec = (const float*)d_in[4];
    float* out   = (float*)d_out;
    float* h_hat = out;
    float* z_out = out + (size_t)NB * DIM;

    const int GEMM_SMEM = STAGES * STG + 1024;    // 97 KB -> 2 CTAs/SM
    cudaFuncSetAttribute(gemm_kernel, cudaFuncAttributeMaxDynamicSharedMemorySize, GEMM_SMEM);
    cudaFuncSetAttribute(topk_kernel, cudaFuncAttributeMaxDynamicSharedMemorySize, LAT * 4);

    // 1) bf16 conversions (rank-only precision)
    convert_h_kernel<<<(unsigned)((size_t)NB * DIM / 2 / 256), 256>>>(h);
    convert_w_kernel<<<(unsigned)((size_t)LAT * DIM / 2 / 256), 256>>>(W_enc);

    // 2) transpose W_dec for coalesced sparse decode
    transpose_kernel<<<dim3(LAT / 32, DIM / 32), dim3(32, 8)>>>(W_dec);

    // 3) encode GEMM (single bf16, mma.sync, always-commit pipeline)
    gemm_kernel<<<(NB / BM) * (LAT / BN), 256, GEMM_SMEM>>>();

    // 4) top-64: radix select + compensated-fp32 candidate refinement
    topk_kernel<<<NB, 512, LAT * 4>>>(h, W_enc, b_enc, z_out);

    // 5) sparse decode
    decode_kernel<<<NB, 512>>>(b_dec, h_hat);

    (void)in_sizes; (void)n_in; (void)out_size;
}

// round 16
// speedup vs baseline: 2.6450x; 1.1958x over previous
#include <cuda_runtime.h>
#include <cuda_bf16.h>
#include <cstdint>

// ---------------------------------------------------------------------------
// Problem constants
// ---------------------------------------------------------------------------
#define DIM   4096
#define LAT   32768
#define NB    4096
#define TOPK  64

// GEMM tiling (single bf16 term)
#define BM      128
#define BN      128
#define BK      64                // bf16 k-elems per stage (128B per tile row)
#define NKSTEP  (DIM / BK)        // 64
#define STAGES  3
#define A_STG   16384             // 128 rows * 128 B
#define B_STG   16384
#define STG     (A_STG + B_STG)   // 32 KB per stage

// candidate band: covers bf16-GEMM sigma (1.1e-3, >15 sigma) + 16-bit key
// quantization (<=0.008 abs near threshold) with huge margin
#define BAND_DELTA 0.045f
#define MAXC 512

// ---------------------------------------------------------------------------
// Device scratch (__device__ globals; no allocation)
// ---------------------------------------------------------------------------
__device__ __nv_bfloat16 g_Ahi[(size_t)NB * DIM];     //  32 MB
__device__ __nv_bfloat16 g_Bhi[(size_t)LAT * DIM];    // 256 MB
__device__ uint32_t g_keys[(size_t)NB * LAT];         // 512 MB sortkeys(z+b)
__device__ float g_WdT[(size_t)LAT * DIM];            // 512 MB

// ---------------------------------------------------------------------------
// PTX helpers (sm_80-level features only; plain compute_103-safe)
// ---------------------------------------------------------------------------
__device__ __forceinline__ uint32_t smem_u32(const void* p) {
    uint32_t a;
    asm("{ .reg .u64 t; cvta.to.shared.u64 t, %1; cvt.u32.u64 %0, t; }" : "=r"(a) : "l"(p));
    return a;
}

#define CP_ASYNC16(dst, src) \
    asm volatile("cp.async.cg.shared.global [%0], [%1], 16;" :: "r"(dst), "l"(src))
#define CP_COMMIT()  asm volatile("cp.async.commit_group;")
#define CP_WAIT(n)   asm volatile("cp.async.wait_group %0;" :: "n"(n))

#define LDSM4(R, addr) \
    asm volatile("ldmatrix.sync.aligned.m8n8.x4.shared.b16 {%0,%1,%2,%3}, [%4];" \
                 : "=r"((R)[0]), "=r"((R)[1]), "=r"((R)[2]), "=r"((R)[3]) : "r"(addr))

#define MMA_BF16(C, A, B0, B1) \
    asm volatile("mma.sync.aligned.m16n8k16.row.col.f32.bf16.bf16.f32 " \
                 "{%0,%1,%2,%3}, {%4,%5,%6,%7}, {%8,%9}, {%0,%1,%2,%3};" \
                 : "+f"((C)[0]), "+f"((C)[1]), "+f"((C)[2]), "+f"((C)[3]) \
                 : "r"((A)[0]), "r"((A)[1]), "r"((A)[2]), "r"((A)[3]), "r"(B0), "r"(B1))

__device__ __forceinline__ unsigned sortkey(float f) {
    unsigned b = __float_as_uint(f);
    return (b & 0x80000000u) ? ~b : (b | 0x80000000u);
}
__device__ __forceinline__ float unsortkey(unsigned u) {
    unsigned b = (u & 0x80000000u) ? (u & 0x7FFFFFFFu) : ~u;
    return __uint_as_float(b);
}

// ---------------------------------------------------------------------------
// bf16 conversion kernels (rank-only precision; exact values recomputed later)
// ---------------------------------------------------------------------------
__global__ void __launch_bounds__(256) convert_h_kernel(const float* __restrict__ h) {
    size_t t = (size_t)blockIdx.x * 256 + threadIdx.x;
    float2 f = ((const float2*)h)[t];
    __nv_bfloat162 v;
    v.x = __float2bfloat16(f.x);
    v.y = __float2bfloat16(f.y);
    ((__nv_bfloat162*)g_Ahi)[t] = v;
}

__global__ void __launch_bounds__(256) convert_w_kernel(const float* __restrict__ W) {
    size_t t = (size_t)blockIdx.x * 256 + threadIdx.x;
    float2 f = ((const float2*)W)[t];
    __nv_bfloat162 v;
    v.x = __float2bfloat16(f.x);
    v.y = __float2bfloat16(f.y);
    ((__nv_bfloat162*)g_Bhi)[t] = v;
}

// ---------------------------------------------------------------------------
// Transpose W_dec [DIM, LAT] -> g_WdT [LAT, DIM]
// ---------------------------------------------------------------------------
__global__ void __launch_bounds__(256) transpose_kernel(const float* __restrict__ Wd) {
    __shared__ float tile[32][33];
    int lbase = blockIdx.x * 32, dbase = blockIdx.y * 32;
    int tx = threadIdx.x, ty = threadIdx.y;   // (32, 8)
#pragma unroll
    for (int j = 0; j < 4; ++j)
        tile[ty + j * 8][tx] = Wd[(size_t)(dbase + ty + j * 8) * LAT + lbase + tx];
    __syncthreads();
#pragma unroll
    for (int j = 0; j < 4; ++j)
        g_WdT[(size_t)(lbase + ty + j * 8) * DIM + dbase + tx] = tile[tx][ty + j * 8];
}

// ---------------------------------------------------------------------------
// Encode GEMM: keys = sortkey(h @ W_enc^T + b_enc), single bf16, mma.sync
// CTA 128x128, 8 warps (4M x 2N), 3-stage cp.async, SW128 swizzle, BK=64,
// 2 CTAs/SM. CP_COMMIT every iteration so CP_WAIT is ALWAYS binding.
// ---------------------------------------------------------------------------
__device__ __forceinline__ void load_stage(uint32_t sbase, int slot, int kt,
                                           int m0, int n0, int tid) {
    uint32_t stg = sbase + slot * STG;
    int t = tid & 127;
    bool isB = tid >= 128;
    int base_row = isB ? n0 : m0;
    const __nv_bfloat16* src_base = isB ? g_Bhi : g_Ahi;
    uint32_t dst0 = stg + (isB ? A_STG : 0);
#pragma unroll
    for (int j = 0; j < 8; ++j) {
        int gid = j * 128 + t;
        int row = gid >> 3;        // 0..127
        int g   = gid & 7;         // 16B granule: k offset g*8 elems
        const __nv_bfloat16* src =
            src_base + (size_t)(base_row + row) * DIM + kt + g * 8;
        uint32_t col = (uint32_t)g * 16;
        uint32_t dst = dst0 + row * 128 + (col ^ (((uint32_t)row & 7) << 4));
        CP_ASYNC16(dst, src);
    }
}

__global__ void __launch_bounds__(256, 2) gemm_kernel(const float* __restrict__ b_enc) {
    extern __shared__ char smraw[];
    uint32_t sbase = (smem_u32(smraw) + 1023u) & ~1023u;

    int tid  = threadIdx.x;
    int lane = tid & 31;
    int wid  = tid >> 5;
    int m_tile = blockIdx.x & 31;       // M fastest -> B tiles shared by 32 CTAs
    int n_tile = blockIdx.x >> 5;
    int m0 = m_tile * BM, n0 = n_tile * BN;
    int mw = (wid & 3) * 32;
    int nw = (wid >> 2) * 64;

    float acc[2][8][4];
#pragma unroll
    for (int a = 0; a < 2; ++a)
#pragma unroll
        for (int b = 0; b < 8; ++b)
#pragma unroll
            for (int c = 0; c < 4; ++c) acc[a][b][c] = 0.0f;

    load_stage(sbase, 0, 0, m0, n0, tid);  CP_COMMIT();
    load_stage(sbase, 1, BK, m0, n0, tid); CP_COMMIT();

    int rowA0 = mw + (lane & 15);
    int rowB0 = nw + (lane & 7) + ((lane & 16) ? 8 : 0);
    uint32_t khA = (lane & 16) ? 16u : 0u;
    uint32_t khB = (lane & 8)  ? 16u : 0u;

    int cons = 0, prod = 2;
#pragma unroll 1
    for (int ks = 0; ks < NKSTEP; ++ks) {
        CP_WAIT(STAGES - 2);
        __syncthreads();

        int nxt = ks + STAGES - 1;
        if (nxt < NKSTEP) load_stage(sbase, prod, nxt * BK, m0, n0, tid);
        CP_COMMIT();    // unconditional: keeps group accounting uniform

        uint32_t sA = sbase + cons * STG;
        uint32_t sB = sA + A_STG;

#pragma unroll
        for (int ksub = 0; ksub < 4; ++ksub) {      // 4 x k16 per 128B row
            uint32_t aH[2][4], bH[8][2];
            uint32_t kb = (uint32_t)ksub * 32;

#pragma unroll
            for (int mi = 0; mi < 2; ++mi) {
                int row = rowA0 + mi * 16;
                uint32_t xr = ((uint32_t)row & 7) << 4;
                LDSM4(aH[mi], sA + row * 128 + ((kb + khA) ^ xr));
            }
#pragma unroll
            for (int ni = 0; ni < 4; ++ni) {
                int row = rowB0 + ni * 16;
                uint32_t xr = ((uint32_t)row & 7) << 4;
                uint32_t rh[4];
                LDSM4(rh, sB + row * 128 + ((kb + khB) ^ xr));
                bH[2 * ni][0] = rh[0]; bH[2 * ni][1] = rh[1];
                bH[2 * ni + 1][0] = rh[2]; bH[2 * ni + 1][1] = rh[3];
            }
#pragma unroll
            for (int mi = 0; mi < 2; ++mi)
#pragma unroll
                for (int t8 = 0; t8 < 8; ++t8)
                    MMA_BF16(acc[mi][t8], aH[mi], bH[t8][0], bH[t8][1]);
        }

        cons = (cons == STAGES - 1) ? 0 : cons + 1;
        prod = (prod == STAGES - 1) ? 0 : prod + 1;
    }

    // epilogue: fold bias, write monotone sortkeys directly
#pragma unroll
    for (int mi = 0; mi < 2; ++mi) {
#pragma unroll
        for (int t8 = 0; t8 < 8; ++t8) {
            int row = m0 + mw + mi * 16 + (lane >> 2);
            int col = n0 + nw + t8 * 8 + (lane & 3) * 2;
            float b0 = b_enc[col], b1 = b_enc[col + 1];
            uint2 k0 = make_uint2(sortkey(acc[mi][t8][0] + b0),
                                  sortkey(acc[mi][t8][1] + b1));
            uint2 k1 = make_uint2(sortkey(acc[mi][t8][2] + b0),
                                  sortkey(acc[mi][t8][3] + b1));
            *(uint2*)&g_keys[(size_t)row * LAT + col]       = k0;
            *(uint2*)&g_keys[(size_t)(row + 8) * LAT + col] = k1;
        }
    }
}

// ---------------------------------------------------------------------------
// Fused per-row: 16-bit 2-pass radix select (per-warp histograms), exact
// compensated-fp32 candidate recompute, dense z scatter, sparse decode.
// NO bulk fp64 (R13: +7.5ms), NO plain fp32 dots (R12/R14: rank errors).
// ---------------------------------------------------------------------------
__device__ __forceinline__ void dot2_acc(float a, float b, float& s, float& c) {
    float ph = a * b;
    float pl = fmaf(a, b, -ph);      // exact product residual
    float t  = s + ph;               // TwoSum
    float z  = t - s;
    float e  = (s - (t - z)) + (ph - z);
    s = t;
    c += e + pl;
}

__global__ void __launch_bounds__(512, 2) topk_decode_kernel(
    const float* __restrict__ h, const float* __restrict__ W_enc,
    const float* __restrict__ b_enc, const float* __restrict__ b_dec,
    float* __restrict__ z_out, float* __restrict__ h_hat)
{
    extern __shared__ unsigned char dynsm[];
    unsigned short* skeys = (unsigned short*)dynsm;          // 64 KB
    unsigned* whist = (unsigned*)(dynsm + 65536);            // 16 KB (16 warps x 256)

    __shared__ unsigned hist[256];
    __shared__ unsigned sh_hi, sh_rem, sh_t16, sh_ncand;
    __shared__ int   cidx[MAXC];
    __shared__ float cval[MAXC];
    __shared__ unsigned char csel[MAXC];
    __shared__ int   sidx[TOPK];
    __shared__ float sval[TOPK];

    int row  = blockIdx.x;
    int tid  = threadIdx.x;
    int lane = tid & 31;
    int wid  = tid >> 5;

    // ---- load keys, keep high 16 bits in smem ----
    const uint32_t* kp = g_keys + (size_t)row * LAT;
    for (int i = tid * 4; i < LAT; i += 2048) {
        uint4 v = *(const uint4*)(kp + i);
        unsigned a = (v.x >> 16) | (v.y & 0xFFFF0000u);
        unsigned b = (v.z >> 16) | (v.w & 0xFFFF0000u);
        *(uint2*)(skeys + i) = make_uint2(a, b);
    }
    for (int i = tid; i < 4096; i += 512) whist[i] = 0;
    if (tid == 0) sh_ncand = 0;
    __syncthreads();

    // ---- radix pass 1: bits [15:8], per-warp histograms ----
    unsigned* myh = whist + (wid << 8);
    for (int i = tid; i < LAT; i += 512) atomicAdd(&myh[skeys[i] >> 8], 1u);
    __syncthreads();
    if (tid < 256) {
        unsigned s = 0;
#pragma unroll
        for (int w = 0; w < 16; ++w) s += whist[(w << 8) + tid];
        hist[tid] = s;
    }
    __syncthreads();
    if (tid == 0) {
        unsigned rem = TOPK;
        int b = 255;
        for (; b > 0; --b) { unsigned c = hist[b]; if (c >= rem) break; rem -= c; }
        sh_hi = (unsigned)b; sh_rem = rem;
    }
    __syncthreads();
    unsigned hi = sh_hi;

    // ---- radix pass 2: bits [7:0] among keys with matching high byte ----
    for (int i = tid; i < 4096; i += 512) whist[i] = 0;
    __syncthreads();
    for (int i = tid; i < LAT; i += 512) {
        unsigned k = skeys[i];
        if ((k >> 8) == hi) atomicAdd(&myh[k & 255u], 1u);
    }
    __syncthreads();
    if (tid < 256) {
        unsigned s = 0;
#pragma unroll
        for (int w = 0; w < 16; ++w) s += whist[(w << 8) + tid];
        hist[tid] = s;
    }
    __syncthreads();
    if (tid == 0) {
        unsigned rem = sh_rem;
        int b = 255;
        for (; b > 0; --b) { unsigned c = hist[b]; if (c >= rem) break; rem -= c; }
        sh_t16 = (hi << 8) | (unsigned)b;
    }
    __syncthreads();

    float    Tv    = unsortkey(sh_t16 << 16);         // bucket lower bound
    unsigned keyLo = sortkey(Tv - BAND_DELTA) >> 16;

    // ---- candidates: everything that could be a true top-64 member ----
    for (int i = tid; i < LAT; i += 512) {
        if ((unsigned)skeys[i] >= keyLo) {
            unsigned s = atomicAdd(&sh_ncand, 1u);
            if (s < MAXC) cidx[s] = i;
        }
    }
    __syncthreads();
    int nc = (int)sh_ncand; if (nc > MAXC) nc = MAXC;

    // ---- compensated fp32 dot per candidate (one warp per candidate) ----
    const float* hrow = h + (size_t)row * DIM;
    for (int c = wid; c < nc; c += 16) {
        int l = cidx[c];
        const float* wrow = W_enc + (size_t)l * DIM;
        float s = 0.0f, comp = 0.0f;
#pragma unroll 4
        for (int i = lane * 4; i < DIM; i += 128) {
            float4 hv = *(const float4*)(hrow + i);
            float4 wv = *(const float4*)(wrow + i);
            dot2_acc(hv.x, wv.x, s, comp);
            dot2_acc(hv.y, wv.y, s, comp);
            dot2_acc(hv.z, wv.z, s, comp);
            dot2_acc(hv.w, wv.w, s, comp);
        }
        double p = (double)s + (double)comp;
#pragma unroll
        for (int off = 16; off > 0; off >>= 1) p += __shfl_xor_sync(0xFFFFFFFFu, p, off);
        if (lane == 0) cval[c] = (float)(p + (double)b_enc[l]);
    }
    __syncthreads();

    // ---- exact ranking among candidates (jax tie order: lower idx first) ----
    if (tid < nc) {
        float v = cval[tid]; int id = cidx[tid];
        int r = 0;
        for (int m = 0; m < nc; ++m)
            if (cval[m] > v || (cval[m] == v && cidx[m] < id)) r++;
        csel[tid] = (r < TOPK) ? 1 : 0;
    }
    __syncthreads();

    // ---- dense z: zeros then scatter exact relu'd winners; compact lists ----
    float* zr = z_out + (size_t)row * LAT;
    for (int i = tid; i < LAT; i += 512) zr[i] = 0.0f;
    __syncthreads();
    if (tid < nc && csel[tid]) {
        float relv = fmaxf(cval[tid], 0.0f);
        zr[cidx[tid]] = relv;
        int slot = 0;
        for (int m = 0; m < nc; ++m)
            if (csel[m] && cidx[m] < cidx[tid]) slot++;
        sidx[slot] = cidx[tid];
        sval[slot] = relv;
    }
    __syncthreads();

    // ---- fused sparse decode: h_hat[row] = b_dec + sum_k val_k*WdT[idx_k,:] ----
    int d0 = tid * 8;
    float4 a0 = *(const float4*)(b_dec + d0);
    float4 a1 = *(const float4*)(b_dec + d0 + 4);
#pragma unroll 4
    for (int k = 0; k < TOPK; ++k) {
        const float4* w = (const float4*)(g_WdT + (size_t)sidx[k] * DIM + d0);
        float v = sval[k];
        float4 w0 = w[0], w1 = w[1];
        a0.x += v * w0.x; a0.y += v * w0.y; a0.z += v * w0.z; a0.w += v * w0.w;
        a1.x += v * w1.x; a1.y += v * w1.y; a1.z += v * w1.z; a1.w += v * w1.w;
    }
    *(float4*)(h_hat + (size_t)row * DIM + d0)     = a0;
    *(float4*)(h_hat + (size_t)row * DIM + d0 + 4) = a1;
}

// ---------------------------------------------------------------------------
// Launch: inputs h, W_enc, b_enc, W_dec, b_dec; out = [h_hat | z]
// ---------------------------------------------------------------------------
extern "C" void kernel_launch(void* const* d_in, const int* in_sizes, int n_in,
                              void* d_out, int out_size) {
    const float* h     = (const float*)d_in[0];
    const float* W_enc = (const float*)d_in[1];
    const float* b_enc = (const float*)d_in[2];
    const float* W_dec = (const float*)d_in[3];
    const float* b_dec = (const float*)d_in[4];
    float* out   = (float*)d_out;
    float* h_hat = out;
    float* z_out = out + (size_t)NB * DIM;

    const int GEMM_SMEM = STAGES * STG + 1024;    // 97 KB -> 2 CTAs/SM
    const int TOPK_SMEM = 65536 + 16384;          // 80 KB dyn -> 2 CTAs/SM
    cudaFuncSetAttribute(gemm_kernel, cudaFuncAttributeMaxDynamicSharedMemorySize, GEMM_SMEM);
    cudaFuncSetAttribute(topk_decode_kernel, cudaFuncAttributeMaxDynamicSharedMemorySize, TOPK_SMEM);

    // 1) bf16 conversions (rank-only precision)
    convert_h_kernel<<<(unsigned)((size_t)NB * DIM / 2 / 256), 256>>>(h);
    convert_w_kernel<<<(unsigned)((size_t)LAT * DIM / 2 / 256), 256>>>(W_enc);

    // 2) transpose W_dec for coalesced sparse decode
    transpose_kernel<<<dim3(LAT / 32, DIM / 32), dim3(32, 8)>>>(W_dec);

    // 3) encode GEMM (single bf16, bias folded, sortkeys out)
    gemm_kernel<<<(NB / BM) * (LAT / BN), 256, GEMM_SMEM>>>(b_enc);

    // 4) fused: 16-bit radix top-64 + exact refinement + z + decode
    topk_decode_kernel<<<NB, 512, TOPK_SMEM>>>(h, W_enc, b_enc, b_dec, z_out, h_hat);

    (void)in_sizes; (void)n_in; (void)out_size;
}